// round 4
// baseline (speedup 1.0000x reference)
#include <cuda_runtime.h>
#include <cuda_bf16.h>

#define N_NODES 100000
#define N_EDGES 1600000
#define IN_DIM  128
#define HID_DIM 64
#define OUT_DIM 40

// ---------------- scratch (static device globals; no runtime alloc) --------
__device__              int    g_is64;
__device__ __align__(16) float g_deg [N_NODES];
__device__ __align__(16) float g_dinv[N_NODES];
__device__              int    g_src [N_EDGES];
__device__              int    g_dst [N_EDGES];
__device__              float  g_norm[N_EDGES];
__device__ __align__(16) float g_h1  [(size_t)N_NODES * HID_DIM];   // x@W1
__device__ __align__(16) float g_agg1[(size_t)N_NODES * HID_DIM];   // aggregated (no bias)
__device__ __align__(16) float g_h2  [(size_t)N_NODES * OUT_DIM];   // relu(agg1+b1)@W2

__device__ __forceinline__ void redg_f32(float* p, float v) {
    asm volatile("red.global.add.f32 [%0], %1;" :: "l"(p), "f"(v) : "memory");
}

// ---------------- dtype detection: int32 vs int64 edge_index ---------------
// Values are < 100000 (< 2^31). If stored as int64 (little endian), every odd
// 32-bit word is 0. If stored as int32, odd words are random node ids
// (P(zero) ~ 1e-5 each) -> 64 zero odd words identifies int64 conclusively.
__global__ void k_detect(const unsigned* __restrict__ w) {
    if (threadIdx.x == 0 && blockIdx.x == 0) {
        int all0 = 1;
        for (int i = 0; i < 64; i++)
            if (w[2 * i + 1] != 0u) { all0 = 0; break; }
        g_is64 = all0;
    }
}

// extract src/dst as int32 regardless of stored width
__global__ void k_extract(const unsigned* __restrict__ w) {
    int e = blockIdx.x * blockDim.x + threadIdx.x;
    if (e >= N_EDGES) return;
    if (g_is64) {
        g_src[e] = (int)w[2 * e];                    // low word of int64
        g_dst[e] = (int)w[2 * (N_EDGES + e)];
    } else {
        g_src[e] = (int)w[e];
        g_dst[e] = (int)w[N_EDGES + e];
    }
}

// ---------------- degree / norm precompute --------------------------------
__global__ void k_init_deg() {
    int i = blockIdx.x * blockDim.x + threadIdx.x;
    if (i < N_NODES) g_deg[i] = 1.0f;               // implicit self loop
}

__global__ void k_deg_accum() {
    int e = blockIdx.x * blockDim.x + threadIdx.x;
    if (e < N_EDGES) redg_f32(&g_deg[g_dst[e]], 1.0f);
}

__global__ void k_rsqrt() {
    int i = blockIdx.x * blockDim.x + threadIdx.x;
    if (i < N_NODES) g_dinv[i] = rsqrtf(g_deg[i]);
}

__global__ void k_norm() {
    int e = blockIdx.x * blockDim.x + threadIdx.x;
    if (e < N_EDGES) g_norm[e] = g_dinv[g_src[e]] * g_dinv[g_dst[e]];
}

// ---------------- layer 1 GEMM: h1 = x @ W1; agg1 init with self loop ------
__global__ __launch_bounds__(256) void k_gemm1(const float* __restrict__ x,
                                               const float* __restrict__ W1) {
    __shared__ float Ws[IN_DIM * HID_DIM];          // 32 KB
    {
        float4* dsh = (float4*)Ws;
        const float4* ssh = (const float4*)W1;
        for (int i = threadIdx.x; i < IN_DIM * HID_DIM / 4; i += blockDim.x)
            dsh[i] = ssh[i];
    }
    __syncthreads();

    int node = blockIdx.x * blockDim.x + threadIdx.x;
    if (node >= N_NODES) return;

    float acc[HID_DIM];
#pragma unroll
    for (int j = 0; j < HID_DIM; j++) acc[j] = 0.0f;

    const float4* xr = (const float4*)(x + (size_t)node * IN_DIM);
#pragma unroll 2
    for (int kk = 0; kk < IN_DIM / 4; ++kk) {
        float4 xv = xr[kk];
        float xs[4] = {xv.x, xv.y, xv.z, xv.w};
#pragma unroll
        for (int q = 0; q < 4; ++q) {
            const float4* wr = (const float4*)&Ws[(kk * 4 + q) * HID_DIM];
#pragma unroll
            for (int j4 = 0; j4 < HID_DIM / 4; ++j4) {
                float4 w = wr[j4];                  // warp-broadcast LDS
                acc[4 * j4 + 0] += xs[q] * w.x;
                acc[4 * j4 + 1] += xs[q] * w.y;
                acc[4 * j4 + 2] += xs[q] * w.z;
                acc[4 * j4 + 3] += xs[q] * w.w;
            }
        }
    }

    float di = g_dinv[node];
    float sl = di * di;                             // self-loop coefficient
    size_t base = (size_t)node * HID_DIM;
#pragma unroll
    for (int j4 = 0; j4 < HID_DIM / 4; ++j4) {
        float4 h;
        h.x = acc[4 * j4 + 0]; h.y = acc[4 * j4 + 1];
        h.z = acc[4 * j4 + 2]; h.w = acc[4 * j4 + 3];
        *(float4*)&g_h1[base + 4 * j4] = h;
        float4 a;
        a.x = h.x * sl; a.y = h.y * sl; a.z = h.z * sl; a.w = h.w * sl;
        *(float4*)&g_agg1[base + 4 * j4] = a;
    }
}

// ---------------- layer 1 edge aggregation (scalar REDG) -------------------
__global__ __launch_bounds__(256) void k_agg1() {
    int idx = blockIdx.x * blockDim.x + threadIdx.x;    // E * 16 items
    if (idx >= N_EDGES * 16) return;
    int e = idx >> 4;
    int c = (idx & 15) << 2;                            // float offset, 16B aligned
    int s = g_src[e];
    int d = g_dst[e];
    float nrm = g_norm[e];
    float4 v = *(const float4*)&g_h1[(size_t)s * HID_DIM + c];
    float* p = &g_agg1[(size_t)d * HID_DIM + c];
    redg_f32(p + 0, v.x * nrm);
    redg_f32(p + 1, v.y * nrm);
    redg_f32(p + 2, v.z * nrm);
    redg_f32(p + 3, v.w * nrm);
}

// ------- layer 2 GEMM: h2 = relu(agg1 + b1) @ W2; out init = h2*d^2 + b2 ---
__global__ __launch_bounds__(256) void k_gemm2(const float* __restrict__ W2,
                                               const float* __restrict__ b1,
                                               const float* __restrict__ b2,
                                               float* __restrict__ out) {
    __shared__ float Ws[HID_DIM * OUT_DIM];         // 10 KB
    __shared__ float b1s[HID_DIM];
    __shared__ float b2s[OUT_DIM];
    for (int i = threadIdx.x; i < HID_DIM * OUT_DIM; i += blockDim.x) Ws[i] = W2[i];
    for (int i = threadIdx.x; i < HID_DIM; i += blockDim.x) b1s[i] = b1[i];
    for (int i = threadIdx.x; i < OUT_DIM; i += blockDim.x) b2s[i] = b2[i];
    __syncthreads();

    int node = blockIdx.x * blockDim.x + threadIdx.x;
    if (node >= N_NODES) return;

    float acc[OUT_DIM];
#pragma unroll
    for (int j = 0; j < OUT_DIM; j++) acc[j] = 0.0f;

    size_t ibase = (size_t)node * HID_DIM;
#pragma unroll 2
    for (int k4 = 0; k4 < HID_DIM / 4; ++k4) {
        float4 a = *(const float4*)&g_agg1[ibase + 4 * k4];
        float vin[4];
        vin[0] = fmaxf(a.x + b1s[4 * k4 + 0], 0.0f);
        vin[1] = fmaxf(a.y + b1s[4 * k4 + 1], 0.0f);
        vin[2] = fmaxf(a.z + b1s[4 * k4 + 2], 0.0f);
        vin[3] = fmaxf(a.w + b1s[4 * k4 + 3], 0.0f);
#pragma unroll
        for (int q = 0; q < 4; ++q) {
            const float4* wr = (const float4*)&Ws[(4 * k4 + q) * OUT_DIM];
#pragma unroll
            for (int j4 = 0; j4 < OUT_DIM / 4; ++j4) {
                float4 w = wr[j4];
                acc[4 * j4 + 0] += vin[q] * w.x;
                acc[4 * j4 + 1] += vin[q] * w.y;
                acc[4 * j4 + 2] += vin[q] * w.z;
                acc[4 * j4 + 3] += vin[q] * w.w;
            }
        }
    }

    float di = g_dinv[node];
    float sl = di * di;
    size_t ob = (size_t)node * OUT_DIM;
#pragma unroll
    for (int j4 = 0; j4 < OUT_DIM / 4; ++j4) {
        float4 h;
        h.x = acc[4 * j4 + 0]; h.y = acc[4 * j4 + 1];
        h.z = acc[4 * j4 + 2]; h.w = acc[4 * j4 + 3];
        *(float4*)&g_h2[ob + 4 * j4] = h;
        float4 o;
        o.x = h.x * sl + b2s[4 * j4 + 0];
        o.y = h.y * sl + b2s[4 * j4 + 1];
        o.z = h.z * sl + b2s[4 * j4 + 2];
        o.w = h.w * sl + b2s[4 * j4 + 3];
        *(float4*)&out[ob + 4 * j4] = o;
    }
}

// ---------------- layer 2 edge aggregation ---------------------------------
__global__ __launch_bounds__(256) void k_agg2(float* __restrict__ out) {
    int idx = blockIdx.x * blockDim.x + threadIdx.x;    // E * 10 items
    if (idx >= N_EDGES * 10) return;
    int e = idx / 10;
    int c = (idx - e * 10) * 4;                         // float offset, 16B aligned
    int s = g_src[e];
    int d = g_dst[e];
    float nrm = g_norm[e];
    float4 v = *(const float4*)&g_h2[(size_t)s * OUT_DIM + c];
    float* p = &out[(size_t)d * OUT_DIM + c];
    redg_f32(p + 0, v.x * nrm);
    redg_f32(p + 1, v.y * nrm);
    redg_f32(p + 2, v.z * nrm);
    redg_f32(p + 3, v.w * nrm);
}

// ---------------- launcher -------------------------------------------------
extern "C" void kernel_launch(void* const* d_in, const int* in_sizes, int n_in,
                              void* d_out, int out_size) {
    const float*    x  = (const float*)d_in[0];
    const unsigned* ei = (const unsigned*)d_in[1];   // int32 OR int64 words
    const float*    W1 = (const float*)d_in[2];
    const float*    b1 = (const float*)d_in[3];
    const float*    W2 = (const float*)d_in[4];
    const float*    b2 = (const float*)d_in[5];
    float* out = (float*)d_out;

    const int T = 256;
    k_detect   <<<1, 32>>>(ei);
    k_extract  <<<(N_EDGES + T - 1) / T, T>>>(ei);
    k_init_deg <<<(N_NODES + T - 1) / T, T>>>();
    k_deg_accum<<<(N_EDGES + T - 1) / T, T>>>();
    k_rsqrt    <<<(N_NODES + T - 1) / T, T>>>();
    k_norm     <<<(N_EDGES + T - 1) / T, T>>>();
    k_gemm1    <<<(N_NODES + T - 1) / T, T>>>(x, W1);
    k_agg1     <<<(N_EDGES * 16 + T - 1) / T, T>>>();
    k_gemm2    <<<(N_NODES + T - 1) / T, T>>>(W2, b1, b2, out);
    k_agg2     <<<(N_EDGES * 10 + T - 1) / T, T>>>(out);
}

// round 6
// speedup vs baseline: 1.5383x; 1.5383x over previous
#include <cuda_runtime.h>
#include <cuda_bf16.h>

#define N_NODES 100000
#define N_EDGES 1600000
#define IN_DIM  128
#define HID_DIM 64
#define OUT_DIM 40

// ---------------- scratch (static device globals; no runtime alloc) --------
__device__              int    g_is64;
__device__ __align__(16) float g_deg [N_NODES];
__device__ __align__(16) float g_dinv[N_NODES];
__device__              int    g_src [N_EDGES];
__device__              int    g_dst [N_EDGES];
__device__              float  g_norm[N_EDGES];
__device__ __align__(16) float g_h1  [(size_t)N_NODES * HID_DIM];   // x@W1
__device__ __align__(16) float g_agg1[(size_t)N_NODES * HID_DIM];   // aggregated (no bias)
__device__ __align__(16) float g_h2  [(size_t)N_NODES * OUT_DIM];   // relu(agg1+b1)@W2

__device__ __forceinline__ void redg_f32(float* p, float v) {
    asm volatile("red.global.add.f32 [%0], %1;" :: "l"(p), "f"(v) : "memory");
}
__device__ __forceinline__ void redg_v4(float* p, float a, float b, float c, float d) {
    asm volatile("red.global.add.v4.f32 [%0], {%1, %2, %3, %4};"
                 :: "l"(p), "f"(a), "f"(b), "f"(c), "f"(d) : "memory");
}

// ---------------- dtype detection: int32 vs int64 edge_index ---------------
__global__ void k_detect(const unsigned* __restrict__ w) {
    if (threadIdx.x == 0 && blockIdx.x == 0) {
        int all0 = 1;
        for (int i = 0; i < 64; i++)
            if (w[2 * i + 1] != 0u) { all0 = 0; break; }
        g_is64 = all0;
    }
}

__global__ void k_init_deg() {
    int i = blockIdx.x * blockDim.x + threadIdx.x;
    if (i < N_NODES) g_deg[i] = 1.0f;               // implicit self loop
}

// extract src/dst as int32 (either stored width) + accumulate degree
__global__ void k_extract(const unsigned* __restrict__ w) {
    int e = blockIdx.x * blockDim.x + threadIdx.x;
    if (e >= N_EDGES) return;
    int s, d;
    if (g_is64) {
        s = (int)w[2 * e];                           // low word of int64
        d = (int)w[2 * (N_EDGES + e)];
    } else {
        s = (int)w[e];
        d = (int)w[N_EDGES + e];
    }
    g_src[e] = s;
    g_dst[e] = d;
    redg_f32(&g_deg[d], 1.0f);
}

__global__ void k_rsqrt() {
    int i = blockIdx.x * blockDim.x + threadIdx.x;
    if (i < N_NODES) g_dinv[i] = rsqrtf(g_deg[i]);
}

__global__ void k_norm() {
    int e = blockIdx.x * blockDim.x + threadIdx.x;
    if (e < N_EDGES) g_norm[e] = g_dinv[g_src[e]] * g_dinv[g_dst[e]];
}

// ---------------- layer 1 GEMM: h1 = x @ W1; agg1 init with self loop ------
__global__ __launch_bounds__(256) void k_gemm1(const float* __restrict__ x,
                                               const float* __restrict__ W1) {
    __shared__ float Ws[IN_DIM * HID_DIM];          // 32 KB
    {
        float4* dsh = (float4*)Ws;
        const float4* ssh = (const float4*)W1;
        for (int i = threadIdx.x; i < IN_DIM * HID_DIM / 4; i += blockDim.x)
            dsh[i] = ssh[i];
    }
    __syncthreads();

    int node = blockIdx.x * blockDim.x + threadIdx.x;
    if (node >= N_NODES) return;

    float acc[HID_DIM];
#pragma unroll
    for (int j = 0; j < HID_DIM; j++) acc[j] = 0.0f;

    const float4* xr = (const float4*)(x + (size_t)node * IN_DIM);
#pragma unroll 2
    for (int kk = 0; kk < IN_DIM / 4; ++kk) {
        float4 xv = xr[kk];
        float xs[4] = {xv.x, xv.y, xv.z, xv.w};
#pragma unroll
        for (int q = 0; q < 4; ++q) {
            const float4* wr = (const float4*)&Ws[(kk * 4 + q) * HID_DIM];
#pragma unroll
            for (int j4 = 0; j4 < HID_DIM / 4; ++j4) {
                float4 w = wr[j4];                  // warp-broadcast LDS
                acc[4 * j4 + 0] += xs[q] * w.x;
                acc[4 * j4 + 1] += xs[q] * w.y;
                acc[4 * j4 + 2] += xs[q] * w.z;
                acc[4 * j4 + 3] += xs[q] * w.w;
            }
        }
    }

    float di = g_dinv[node];
    float sl = di * di;                             // self-loop coefficient
    size_t base = (size_t)node * HID_DIM;
#pragma unroll
    for (int j4 = 0; j4 < HID_DIM / 4; ++j4) {
        float4 h;
        h.x = acc[4 * j4 + 0]; h.y = acc[4 * j4 + 1];
        h.z = acc[4 * j4 + 2]; h.w = acc[4 * j4 + 3];
        *(float4*)&g_h1[base + 4 * j4] = h;
        float4 a;
        a.x = h.x * sl; a.y = h.y * sl; a.z = h.z * sl; a.w = h.w * sl;
        *(float4*)&g_agg1[base + 4 * j4] = a;
    }
}

// ---------------- layer 1 edge aggregation (vector REDG.128) ---------------
__global__ __launch_bounds__(256) void k_agg1() {
    int idx = blockIdx.x * blockDim.x + threadIdx.x;    // E * 16 items
    if (idx >= N_EDGES * 16) return;
    int e = idx >> 4;
    int c = (idx & 15) << 2;                            // float offset, 16B aligned
    int s = g_src[e];
    int d = g_dst[e];
    float nrm = g_norm[e];
    float4 v = *(const float4*)&g_h1[(size_t)s * HID_DIM + c];
    float* p = &g_agg1[(size_t)d * HID_DIM + c];
    redg_v4(p, v.x * nrm, v.y * nrm, v.z * nrm, v.w * nrm);
}

// ------- layer 2 GEMM: h2 = relu(agg1 + b1) @ W2; out init = h2*d^2 + b2 ---
__global__ __launch_bounds__(256) void k_gemm2(const float* __restrict__ W2,
                                               const float* __restrict__ b1,
                                               const float* __restrict__ b2,
                                               float* __restrict__ out) {
    __shared__ float Ws[HID_DIM * OUT_DIM];         // 10 KB
    __shared__ float b1s[HID_DIM];
    __shared__ float b2s[OUT_DIM];
    for (int i = threadIdx.x; i < HID_DIM * OUT_DIM; i += blockDim.x) Ws[i] = W2[i];
    for (int i = threadIdx.x; i < HID_DIM; i += blockDim.x) b1s[i] = b1[i];
    for (int i = threadIdx.x; i < OUT_DIM; i += blockDim.x) b2s[i] = b2[i];
    __syncthreads();

    int node = blockIdx.x * blockDim.x + threadIdx.x;
    if (node >= N_NODES) return;

    float acc[OUT_DIM];
#pragma unroll
    for (int j = 0; j < OUT_DIM; j++) acc[j] = 0.0f;

    size_t ibase = (size_t)node * HID_DIM;
#pragma unroll 2
    for (int k4 = 0; k4 < HID_DIM / 4; ++k4) {
        float4 a = *(const float4*)&g_agg1[ibase + 4 * k4];
        float vin[4];
        vin[0] = fmaxf(a.x + b1s[4 * k4 + 0], 0.0f);
        vin[1] = fmaxf(a.y + b1s[4 * k4 + 1], 0.0f);
        vin[2] = fmaxf(a.z + b1s[4 * k4 + 2], 0.0f);
        vin[3] = fmaxf(a.w + b1s[4 * k4 + 3], 0.0f);
#pragma unroll
        for (int q = 0; q < 4; ++q) {
            const float4* wr = (const float4*)&Ws[(4 * k4 + q) * OUT_DIM];
#pragma unroll
            for (int j4 = 0; j4 < OUT_DIM / 4; ++j4) {
                float4 w = wr[j4];
                acc[4 * j4 + 0] += vin[q] * w.x;
                acc[4 * j4 + 1] += vin[q] * w.y;
                acc[4 * j4 + 2] += vin[q] * w.z;
                acc[4 * j4 + 3] += vin[q] * w.w;
            }
        }
    }

    float di = g_dinv[node];
    float sl = di * di;
    size_t ob = (size_t)node * OUT_DIM;
#pragma unroll
    for (int j4 = 0; j4 < OUT_DIM / 4; ++j4) {
        float4 h;
        h.x = acc[4 * j4 + 0]; h.y = acc[4 * j4 + 1];
        h.z = acc[4 * j4 + 2]; h.w = acc[4 * j4 + 3];
        *(float4*)&g_h2[ob + 4 * j4] = h;
        float4 o;
        o.x = h.x * sl + b2s[4 * j4 + 0];
        o.y = h.y * sl + b2s[4 * j4 + 1];
        o.z = h.z * sl + b2s[4 * j4 + 2];
        o.w = h.w * sl + b2s[4 * j4 + 3];
        *(float4*)&out[ob + 4 * j4] = o;
    }
}

// ---------------- layer 2 edge aggregation ---------------------------------
__global__ __launch_bounds__(256) void k_agg2(float* __restrict__ out) {
    int idx = blockIdx.x * blockDim.x + threadIdx.x;    // E * 10 items
    if (idx >= N_EDGES * 10) return;
    int e = idx / 10;
    int c = (idx - e * 10) * 4;                         // float offset, 16B aligned
    int s = g_src[e];
    int d = g_dst[e];
    float nrm = g_norm[e];
    float4 v = *(const float4*)&g_h2[(size_t)s * OUT_DIM + c];
    float* p = &out[(size_t)d * OUT_DIM + c];
    redg_v4(p, v.x * nrm, v.y * nrm, v.z * nrm, v.w * nrm);
}

// ---------------- launcher -------------------------------------------------
extern "C" void kernel_launch(void* const* d_in, const int* in_sizes, int n_in,
                              void* d_out, int out_size) {
    const float*    x  = (const float*)d_in[0];
    const unsigned* ei = (const unsigned*)d_in[1];   // int32 OR int64 words
    const float*    W1 = (const float*)d_in[2];
    const float*    b1 = (const float*)d_in[3];
    const float*    W2 = (const float*)d_in[4];
    const float*    b2 = (const float*)d_in[5];
    float* out = (float*)d_out;

    const int T = 256;
    k_detect   <<<1, 32>>>(ei);
    k_init_deg <<<(N_NODES + T - 1) / T, T>>>();
    k_extract  <<<(N_EDGES + T - 1) / T, T>>>(ei);
    k_rsqrt    <<<(N_NODES + T - 1) / T, T>>>();
    k_norm     <<<(N_EDGES + T - 1) / T, T>>>();
    k_gemm1    <<<(N_NODES + T - 1) / T, T>>>(x, W1);
    k_agg1     <<<(N_EDGES * 16 + T - 1) / T, T>>>();
    k_gemm2    <<<(N_NODES + T - 1) / T, T>>>(W2, b1, b2, out);
    k_agg2     <<<(N_EDGES * 10 + T - 1) / T, T>>>(out);
}